// round 6
// baseline (speedup 1.0000x reference)
#include <cuda_runtime.h>
#include <cuda_fp16.h>
#include <cstdint>

#define VNUM   100000
#define KNZ    8
#define BASE   64
#define DIM    9
#define BATCH  16
#define TV     128
#define THREADS 512
#define NCOL   (BATCH * DIM)     // 144
#define NELEM  (TV * DIM)        // 1152
#define SLAB   (BASE * DIM)      // 576

#define ASTR   72                 // A row stride, halves (144 B)
#define BSTR   72                 // B row stride, halves (144 B)
#define SSTR   1156               // stage per-batch stride, floats (pad: conflict-free STS)

// smem byte offsets
#define OFF_B     0                        // fp16 [144][72] = 20736 B (d-major rows)
#define OFF_A16   20736                    // fp16 [128][72] = 18432 B (ends 39168)
#define OFF_AF32  39168                    // f32  [128][64] = 32768 B (ends 71936)
#define OFF_STAGE 20736                    // f32  [16][1156] = 73984 B (aliases A16/Af32)
#define SMEM_TOTAL (OFF_STAGE + BATCH * SSTR * 4)   // 94720 B

__device__ int g_vb_is64;
__device__ __half g_B[NCOL * BSTR];        // precomputed FS^T, row n = d*16 + b

// int64 values in [0,64) have zero odd int32 slots; int32 data has random odd slots.
__global__ void detect_vb_dtype_kernel(const int* __restrict__ vb32) {
    __shared__ int any_nonzero;
    if (threadIdx.x == 0) any_nonzero = 0;
    __syncthreads();
    for (int i = threadIdx.x; i < 4096; i += blockDim.x)
        if (vb32[2 * i + 1] != 0) any_nonzero = 1;
    __syncthreads();
    if (threadIdx.x == 0) g_vb_is64 = (any_nonzero ? 0 : 1);
}

// Build B once: B[n=d*16+b][k] = base_fs[b*576 + k*9 + d]  (fp16)
__global__ void build_B_kernel(const float* __restrict__ base_fs) {
    for (int i = threadIdx.x; i < BATCH * SLAB; i += blockDim.x) {
        const int b = i / SLAB;
        const int r = i - b * SLAB;
        const int k = r / DIM;
        const int d = r - k * DIM;
        g_B[(d * 16 + b) * BSTR + k] = __float2half_rn(base_fs[i]);
    }
}

static __device__ __forceinline__ void mma16816(float c[4],
                                                const uint32_t a[4],
                                                uint32_t b0, uint32_t b1) {
    asm volatile(
        "mma.sync.aligned.m16n8k16.row.col.f32.f16.f16.f32 "
        "{%0,%1,%2,%3}, {%4,%5,%6,%7}, {%8,%9}, {%0,%1,%2,%3};"
        : "+f"(c[0]), "+f"(c[1]), "+f"(c[2]), "+f"(c[3])
        : "r"(a[0]), "r"(a[1]), "r"(a[2]), "r"(a[3]), "r"(b0), "r"(b1));
}

__global__ __launch_bounds__(THREADS, 2)
void skin_mma_kernel(const float* __restrict__ ws,
                     const void*  __restrict__ vb_raw,
                     float* __restrict__ out) {
    extern __shared__ char smem[];
    const int tid = threadIdx.x;
    const int wid = tid >> 5;
    const int lid = tid & 31;
    const int g   = lid >> 2;       // mma group (0..7)
    const int tg  = lid & 3;        // thread-in-group (0..3)
    const int v0  = blockIdx.x * TV;

    // ---- Phase 1: copy precomputed B into smem + zero Af32 ----
    {
        const float4* Bsrc = (const float4*)g_B;
        float4* Bdst = (float4*)(smem + OFF_B);
        #pragma unroll
        for (int it = 0; it < 3; it++) {
            const int i = tid + it * THREADS;
            if (i < (NCOL * BSTR * 2) / 16) Bdst[i] = Bsrc[i];   // 1296 float4
        }
        float4* Az = (float4*)(smem + OFF_AF32);
        const float4 z = make_float4(0.f, 0.f, 0.f, 0.f);
        #pragma unroll
        for (int it = 0; it < 4; it++)                           // 2048 float4
            Az[tid + it * THREADS] = z;
    }
    __syncthreads();

    // ---- Phase 2: softmax (2 threads/vertex) + atomic scatter into Af32 ----
    float* Af32 = (float*)(smem + OFF_AF32);
    if (tid < 2 * TV) {
        const int vloc = tid >> 1;
        const int h    = tid & 1;
        const int v    = v0 + vloc;
        if (v < VNUM) {
            const float4 xw = *(const float4*)(ws + (size_t)v * KNZ + 4 * h);
            float x[4] = {xw.x, xw.y, xw.z, xw.w};
            float mh = fmaxf(fmaxf(x[0], x[1]), fmaxf(x[2], x[3]));
            const float m = fmaxf(mh, __shfl_xor_sync(0xFFFFFFFFu, mh, 1));
            float sh = 0.f;
            #pragma unroll
            for (int j = 0; j < 4; j++) { x[j] = __expf(x[j] - m); sh += x[j]; }
            const float s = sh + __shfl_xor_sync(0xFFFFFFFFu, sh, 1);
            const float inv = 1.f / s;

            int idx[4];
            if (g_vb_is64) {
                const longlong2* ip =
                    (const longlong2*)((const char*)vb_raw + (size_t)v * 64 + h * 32);
                longlong2 i0 = ip[0], i1 = ip[1];
                idx[0] = (int)i0.x; idx[1] = (int)i0.y;
                idx[2] = (int)i1.x; idx[3] = (int)i1.y;
            } else {
                const int4 i4 =
                    *(const int4*)((const char*)vb_raw + (size_t)v * 32 + h * 16);
                idx[0] = i4.x; idx[1] = i4.y; idx[2] = i4.z; idx[3] = i4.w;
            }
            #pragma unroll
            for (int j = 0; j < 4; j++)
                atomicAdd(&Af32[vloc * BASE + idx[j]], x[j] * inv);  // dups merge here
        }
    }
    __syncthreads();

    // ---- Phase 3: convert Af32 -> A16 (pad cols 64..71 never read by mma) ----
    {
        __half2* A16 = (__half2*)(smem + OFF_A16);
        #pragma unroll
        for (int it = 0; it < 8; it++) {                         // 4096 half2
            const int i = tid + it * THREADS;
            const int r = i >> 5;      // row 0..127
            const int p = i & 31;      // half2 col 0..31
            A16[r * (ASTR / 2) + p] =
                __floats2half2_rn(Af32[r * BASE + 2 * p], Af32[r * BASE + 2 * p + 1]);
        }
    }
    __syncthreads();

    // ---- Phase 4: 16 warps; warp = (row-tile pair, col-half): 16 rows x 72 cols ----
    const int Rrow = (wid >> 1) * 16;    // 0,16,...,112
    const int hcol = wid & 1;            // n-tiles [9h, 9h+9)

    uint32_t afr[4][4];
    {
        const char* Abase = smem + OFF_A16 + (Rrow + g) * (ASTR * 2) + 4 * tg;
        #pragma unroll
        for (int ks = 0; ks < 4; ks++) {
            afr[ks][0] = *(const uint32_t*)(Abase + ks * 32);
            afr[ks][1] = *(const uint32_t*)(Abase + ks * 32 + 8 * ASTR * 2);
            afr[ks][2] = *(const uint32_t*)(Abase + ks * 32 + 16);
            afr[ks][3] = *(const uint32_t*)(Abase + ks * 32 + 8 * ASTR * 2 + 16);
        }
    }

    float acc[9][4];
    #pragma unroll
    for (int t = 0; t < 9; t++)
        #pragma unroll
        for (int q = 0; q < 4; q++) acc[t][q] = 0.f;

    {
        const char* Bbase = smem + OFF_B + (hcol * 9 * 8 + g) * (BSTR * 2) + 4 * tg;
        #pragma unroll
        for (int t = 0; t < 9; t++) {
            const char* Bt = Bbase + t * 8 * (BSTR * 2);
            #pragma unroll
            for (int ks = 0; ks < 4; ks++) {
                const uint32_t b0 = *(const uint32_t*)(Bt + ks * 32);
                const uint32_t b1 = *(const uint32_t*)(Bt + ks * 32 + 16);
                mma16816(acc[t], afr[ks], b0, b1);
            }
        }
    }
    __syncthreads();   // all A16/B reads done before stage aliases them

    // ---- Phase 5: C frags -> stage[b][row*9+d]; col n: b=n&15, d=n>>4 ----
    // Conflict-free: bank = (4b + 9g + d) mod 32, d constant per store, b spans
    // 4 distinct even values across tg (SSTR=1156 => 4b term), g spans 8.
    float* stage = (float*)(smem + OFF_STAGE);
    {
        const int r0 = Rrow + g;
        #pragma unroll
        for (int t = 0; t < 9; t++) {
            const int n0 = (hcol * 9 + t) * 8 + 2 * tg;
            const int b0i = n0 & 15, d0 = n0 >> 4;
            const int n1 = n0 + 1;
            const int b1i = n1 & 15, d1 = n1 >> 4;
            stage[b0i * SSTR + r0 * DIM + d0]       = acc[t][0];
            stage[b1i * SSTR + r0 * DIM + d1]       = acc[t][1];
            stage[b0i * SSTR + (r0 + 8) * DIM + d0] = acc[t][2];
            stage[b1i * SSTR + (r0 + 8) * DIM + d1] = acc[t][3];
        }
    }
    __syncthreads();

    // ---- Phase 6: coalesced copy-out (288 float4 per batch plane) ----
    const int nvalid4 = (min(NELEM, (VNUM - v0) * DIM)) >> 2;
    const float4* st4 = (const float4*)stage;                    // plane stride 289
    #pragma unroll
    for (int it = 0; it < 9; it++) {                             // 4608 float4
        const int f  = tid + it * THREADS;
        const int b  = f / (NELEM / 4);
        const int e4 = f - b * (NELEM / 4);
        if (e4 < nvalid4)
            *(float4*)(out + (size_t)b * ((size_t)VNUM * DIM) + (size_t)v0 * DIM + e4 * 4) =
                st4[b * (SSTR / 4) + e4];
    }
}

extern "C" void kernel_launch(void* const* d_in, const int* in_sizes, int n_in,
                              void* d_out, int out_size) {
    const float* base_fs = (const float*)d_in[0];   // [16, 576] f32
    const float* ws      = (const float*)d_in[1];   // [800000] f32
    const void*  vb      = d_in[2];                 // [800000] i64 or i32 (detected)
    // d_in[3] = vv_index: statically repeat(arange(VNUM), 8); unused.
    float* out = (float*)d_out;                     // [16, 100000, 9] f32

    static bool attr_set = false;
    if (!attr_set) {
        cudaFuncSetAttribute(skin_mma_kernel,
                             cudaFuncAttributeMaxDynamicSharedMemorySize, SMEM_TOTAL);
        attr_set = true;
    }

    detect_vb_dtype_kernel<<<1, 256>>>((const int*)vb);
    build_B_kernel<<<1, 256>>>(base_fs);
    const int blocks = (VNUM + TV - 1) / TV;        // 782
    skin_mma_kernel<<<blocks, THREADS, SMEM_TOTAL>>>(ws, vb, out);
}

// round 7
// speedup vs baseline: 1.1339x; 1.1339x over previous
#include <cuda_runtime.h>
#include <cuda_fp16.h>
#include <cstdint>

#define VNUM   100000
#define KNZ    8
#define BASE   64
#define DIM    9
#define BATCH  16
#define TV     128
#define NCOL   (BATCH * DIM)     // 144
#define NELEM  (TV * DIM)        // 1152
#define SLAB   (BASE * DIM)      // 576

#define ASTR   72                // smem A row stride, halves (144 B)
#define BSTR   72                // B row stride, halves (144 B)
#define SSTR   1156              // stage per-batch stride, floats (conflict-free STS)

#define K1_THREADS 256
#define K1_BLOCKS  ((VNUM + K1_THREADS - 1) / K1_THREADS)   // 391
#define K2_THREADS 512
#define K2_BLOCKS  ((VNUM + TV - 1) / TV)                   // 782
#define AROWS      (K1_BLOCKS * K1_THREADS)                 // 100096 (= K2_BLOCKS*TV)

// k2 smem: B fp16 [144][72] @0 (20736 B), A fp16 [128][72] @20736 (18432 B);
// stage f32 [16][1156] aliases everything from 0.
#define OFF_B     0
#define OFF_A     20736
#define SMEM_K2   (BATCH * SSTR * 4)     // 73984 B

__device__ int g_vb_is64;
__device__ __align__(16) __half g_B[NCOL * BSTR];     // FS^T, row n = d*16 + b
__device__ __align__(16) __half g_A[(size_t)AROWS * BASE];  // dense softmax weights

// ---- detect: 1 warp, 64 samples inside first 512 B (safe for either dtype) ----
__global__ void detect_kernel(const int* __restrict__ vb32) {
    const int lane = threadIdx.x;
    const int bad = (vb32[2 * lane + 1] != 0) | (vb32[2 * (lane + 32) + 1] != 0);
    const unsigned m = __ballot_sync(0xFFFFFFFFu, bad);
    if (lane == 0) g_vb_is64 = (m == 0);
}

// ---- k1: softmax + duplicate-merge -> dense fp16 rows of g_A; block 0 builds g_B ----
__global__ __launch_bounds__(K1_THREADS)
void softmax_scatter_kernel(const float* __restrict__ ws,
                            const void*  __restrict__ vb_raw,
                            const float* __restrict__ base_fs) {
    __shared__ __half rows[K1_THREADS][ASTR];   // 36864 B, exclusive row per thread
    const int tid = threadIdx.x;
    const int v   = blockIdx.x * K1_THREADS + tid;

    // zero all rows (2304 float4, 9/thread)
    {
        float4* z = (float4*)rows;
        const float4 zz = make_float4(0.f, 0.f, 0.f, 0.f);
        #pragma unroll
        for (int it = 0; it < 9; it++) z[tid + it * K1_THREADS] = zz;
    }

    // block 0 additionally builds g_B: B[n=d*16+b][k] = base_fs[b*576 + k*9 + d]
    if (blockIdx.x == 0) {
        for (int i = tid; i < BATCH * SLAB; i += K1_THREADS) {
            const int b = i / SLAB;
            const int r = i - b * SLAB;
            const int k = r / DIM;
            const int d = r - k * DIM;
            g_B[(d * 16 + b) * BSTR + k] = __float2half_rn(base_fs[i]);
        }
    }
    __syncthreads();

    if (v < VNUM) {
        const float4* wp = reinterpret_cast<const float4*>(ws + (size_t)v * KNZ);
        float4 a4 = wp[0], b4 = wp[1];
        float x[8] = {a4.x, a4.y, a4.z, a4.w, b4.x, b4.y, b4.z, b4.w};
        float m = x[0];
        #pragma unroll
        for (int j = 1; j < 8; j++) m = fmaxf(m, x[j]);
        float s = 0.f;
        #pragma unroll
        for (int j = 0; j < 8; j++) { x[j] = __expf(x[j] - m); s += x[j]; }
        const float inv = 1.f / s;

        int idx[8];
        if (g_vb_is64) {
            const longlong2* ip =
                reinterpret_cast<const longlong2*>((const char*)vb_raw + (size_t)v * KNZ * 8);
            #pragma unroll
            for (int j = 0; j < 4; j++) {
                longlong2 ii = ip[j];
                idx[2 * j] = (int)ii.x; idx[2 * j + 1] = (int)ii.y;
            }
        } else {
            const int4* ip =
                reinterpret_cast<const int4*>((const char*)vb_raw + (size_t)v * KNZ * 4);
            int4 i0 = ip[0], i1 = ip[1];
            idx[0] = i0.x; idx[1] = i0.y; idx[2] = i0.z; idx[3] = i0.w;
            idx[4] = i1.x; idx[5] = i1.y; idx[6] = i1.z; idx[7] = i1.w;
        }
        // vb sampled with replacement: merge duplicates in fp32, round once
        #pragma unroll
        for (int j = 0; j < 8; j++) {
            bool first = true;
            #pragma unroll
            for (int i = 0; i < 8; i++)
                if (i < j && idx[i] == idx[j]) first = false;
            if (first) {
                float acc = 0.f;
                #pragma unroll
                for (int i = 0; i < 8; i++)
                    if (i >= j && idx[i] == idx[j]) acc += x[i];
                rows[tid][idx[j]] = __float2half_rn(acc * inv);
            }
        }
    }
    __syncthreads();

    // coalesced copy rows -> g_A (2048 float4, 8/thread)
    {
        __half* dst = g_A + (size_t)blockIdx.x * K1_THREADS * BASE;
        #pragma unroll
        for (int it = 0; it < 8; it++) {
            const int f = tid + it * K1_THREADS;
            const int r = f >> 3;
            const int c = f & 7;
            *(float4*)(dst + (size_t)r * BASE + c * 8) = *(const float4*)(&rows[r][c * 8]);
        }
    }
}

static __device__ __forceinline__ void mma16816(float c[4],
                                                const uint32_t a[4],
                                                uint32_t b0, uint32_t b1) {
    asm volatile(
        "mma.sync.aligned.m16n8k16.row.col.f32.f16.f16.f32 "
        "{%0,%1,%2,%3}, {%4,%5,%6,%7}, {%8,%9}, {%0,%1,%2,%3};"
        : "+f"(c[0]), "+f"(c[1]), "+f"(c[2]), "+f"(c[3])
        : "r"(a[0]), "r"(a[1]), "r"(a[2]), "r"(a[3]), "r"(b0), "r"(b1));
}

// ---- k2: D[128,144] = A_tile @ B^T via HMMA; stage; coalesced copy-out ----
__global__ __launch_bounds__(K2_THREADS, 2)
void gemm_kernel(float* __restrict__ out) {
    extern __shared__ char smem[];
    const int tid = threadIdx.x;
    const int wid = tid >> 5;
    const int lid = tid & 31;
    const int g   = lid >> 2;
    const int tg  = lid & 3;
    const int v0  = blockIdx.x * TV;

    // Phase 1: copy B (1296 float4) + A tile (1024 float4, coalesced from g_A)
    {
        const float4* Bsrc = (const float4*)g_B;
        float4* Bdst = (float4*)(smem + OFF_B);
        #pragma unroll
        for (int it = 0; it < 3; it++) {
            const int i = tid + it * K2_THREADS;
            if (i < (NCOL * BSTR * 2) / 16) Bdst[i] = Bsrc[i];
        }
        const float4* Asrc = (const float4*)(g_A + (size_t)v0 * BASE);
        #pragma unroll
        for (int it = 0; it < 2; it++) {
            const int f = tid + it * K2_THREADS;
            const int r = f >> 3;
            const int c = f & 7;
            *(float4*)(smem + OFF_A + r * (ASTR * 2) + c * 16) = Asrc[f];
        }
    }
    __syncthreads();

    // Phase 2: warp = (row-tile pair, col-half): 16 rows x 72 cols
    const int Rrow = (wid >> 1) * 16;
    const int hcol = wid & 1;

    uint32_t afr[4][4];
    {
        const char* Abase = smem + OFF_A + (Rrow + g) * (ASTR * 2) + 4 * tg;
        #pragma unroll
        for (int ks = 0; ks < 4; ks++) {
            afr[ks][0] = *(const uint32_t*)(Abase + ks * 32);
            afr[ks][1] = *(const uint32_t*)(Abase + ks * 32 + 8 * ASTR * 2);
            afr[ks][2] = *(const uint32_t*)(Abase + ks * 32 + 16);
            afr[ks][3] = *(const uint32_t*)(Abase + ks * 32 + 8 * ASTR * 2 + 16);
        }
    }

    float acc[9][4];
    #pragma unroll
    for (int t = 0; t < 9; t++)
        #pragma unroll
        for (int q = 0; q < 4; q++) acc[t][q] = 0.f;

    {
        const char* Bbase = smem + OFF_B + (hcol * 9 * 8 + g) * (BSTR * 2) + 4 * tg;
        #pragma unroll
        for (int t = 0; t < 9; t++) {
            const char* Bt = Bbase + t * 8 * (BSTR * 2);
            #pragma unroll
            for (int ks = 0; ks < 4; ks++) {
                const uint32_t b0 = *(const uint32_t*)(Bt + ks * 32);
                const uint32_t b1 = *(const uint32_t*)(Bt + ks * 32 + 16);
                mma16816(acc[t], afr[ks], b0, b1);
            }
        }
    }
    __syncthreads();   // A/B reads done before stage aliases them

    // Phase 3: C frags -> stage[b][row*9+d]; col n = d*16+b => b=n&15, d=n>>4
    float* stage = (float*)smem;
    {
        const int r0 = Rrow + g;
        #pragma unroll
        for (int t = 0; t < 9; t++) {
            const int n0 = (hcol * 9 + t) * 8 + 2 * tg;
            const int b0i = n0 & 15, d0 = n0 >> 4;
            const int n1 = n0 + 1;
            const int b1i = n1 & 15, d1 = n1 >> 4;
            stage[b0i * SSTR + r0 * DIM + d0]       = acc[t][0];
            stage[b1i * SSTR + r0 * DIM + d1]       = acc[t][1];
            stage[b0i * SSTR + (r0 + 8) * DIM + d0] = acc[t][2];
            stage[b1i * SSTR + (r0 + 8) * DIM + d1] = acc[t][3];
        }
    }
    __syncthreads();

    // Phase 4: coalesced copy-out (288 float4 per batch plane)
    const int nvalid4 = (min(NELEM, (VNUM - v0) * DIM)) >> 2;
    const float4* st4 = (const float4*)stage;
    #pragma unroll
    for (int it = 0; it < 9; it++) {
        const int f  = tid + it * K2_THREADS;
        const int b  = f / (NELEM / 4);
        const int e4 = f - b * (NELEM / 4);
        if (e4 < nvalid4)
            *(float4*)(out + (size_t)b * ((size_t)VNUM * DIM) + (size_t)v0 * DIM + e4 * 4) =
                st4[b * (SSTR / 4) + e4];
    }
}

extern "C" void kernel_launch(void* const* d_in, const int* in_sizes, int n_in,
                              void* d_out, int out_size) {
    const float* base_fs = (const float*)d_in[0];   // [16, 576] f32
    const float* ws      = (const float*)d_in[1];   // [800000] f32
    const void*  vb      = d_in[2];                 // [800000] i64 or i32 (detected)
    // d_in[3] = vv_index: statically repeat(arange(VNUM), 8); unused.
    float* out = (float*)d_out;                     // [16, 100000, 9] f32

    static bool attr_set = false;
    if (!attr_set) {
        cudaFuncSetAttribute(gemm_kernel,
                             cudaFuncAttributeMaxDynamicSharedMemorySize, SMEM_K2);
        attr_set = true;
    }

    detect_kernel<<<1, 32>>>((const int*)vb);
    softmax_scatter_kernel<<<K1_BLOCKS, K1_THREADS>>>(ws, vb, base_fs);
    gemm_kernel<<<K2_BLOCKS, K2_THREADS, SMEM_K2>>>(out);
}